// round 4
// baseline (speedup 1.0000x reference)
#include <cuda_runtime.h>
#include <cstdint>

// Problem constants (fixed shapes for this problem instance)
#define GN   100000      // nodes
#define GE   1600000     // edges
#define GEL  200000      // label edges
#define INC  64
#define POSC 16
#define KH   80          // INC + POSC
#define HID  64
#define OUTC 32
#define NB   98          // scan blocks: ceil(GN / 1024)

// ---------------- scratch (device globals; no allocation allowed) -----------
__device__ float g_dinv[GN];
__device__ float g_hw1 [GN * HID];
__device__ float g_agg1[GN * HID];
__device__ float g_hw2 [GN * OUTC];
__device__ float g_wa  [GN];
__device__ float g_wb  [GN];
__device__ int   g_cnt [GN];        // neighbor count (no self-loop)
__device__ int   g_off [GN];        // CSR row start
__device__ int   g_cur [GN];        // scatter cursor
__device__ int   g_bsum[128];
__device__ int   g_bscan[128];
__device__ int   g_csrc[GE];        // CSR: src node per slot
__device__ float g_cnrm[GE];        // CSR: dinv[src]*dinv[dst] per slot

// ---------------- degree histogram + normalization --------------------------
__global__ void k_zero_cnt(int* cnt) {
    int i = blockIdx.x * blockDim.x + threadIdx.x;
    if (i < GN) cnt[i] = 0;
}

__global__ void k_hist(const int* __restrict__ dst, int* cnt) {
    int i = blockIdx.x * blockDim.x + threadIdx.x;
    if (i < GE) atomicAdd(&cnt[dst[i]], 1);
}

__global__ void k_dinv(const int* __restrict__ cnt, float* dinv) {
    int i = blockIdx.x * blockDim.x + threadIdx.x;
    if (i < GN) dinv[i] = rsqrtf((float)(cnt[i] + 1));   // +1 self-loop
}

// ---------------- exclusive scan of cnt -> off (3 kernels) ------------------
// 1024 elements per block, 256 threads, 4 sequential elems per thread.
__global__ void k_scan_local(const int* __restrict__ cnt, int* off, int* bsum) {
    __shared__ int s[256];
    const int b = blockIdx.x, t = threadIdx.x;
    const int i0 = b * 1024 + t * 4;
    int v[4]; int sum = 0;
#pragma unroll
    for (int j = 0; j < 4; j++) {
        int idx = i0 + j;
        int c = (idx < GN) ? cnt[idx] : 0;
        v[j] = sum; sum += c;
    }
    s[t] = sum;
    __syncthreads();
    for (int d = 1; d < 256; d <<= 1) {          // inclusive Hillis-Steele
        int x = (t >= d) ? s[t - d] : 0;
        __syncthreads();
        s[t] += x;
        __syncthreads();
    }
    int base = (t > 0) ? s[t - 1] : 0;
#pragma unroll
    for (int j = 0; j < 4; j++) {
        int idx = i0 + j;
        if (idx < GN) off[idx] = base + v[j];
    }
    if (t == 255) bsum[b] = s[255];
}

__global__ void k_scan_bsum(const int* __restrict__ bsum, int* bscan) {
    __shared__ int s[128];
    int t = threadIdx.x;
    s[t] = (t < NB) ? bsum[t] : 0;
    __syncthreads();
    for (int d = 1; d < 128; d <<= 1) {
        int x = (t >= d) ? s[t - d] : 0;
        __syncthreads();
        s[t] += x;
        __syncthreads();
    }
    if (t < NB) bscan[t] = (t > 0) ? s[t - 1] : 0;
}

__global__ void k_scan_add(int* off, int* cur, const int* __restrict__ bscan) {
    const int b = blockIdx.x, t = threadIdx.x;
    const int add = bscan[b];
    const int i0 = b * 1024 + t * 4;
#pragma unroll
    for (int j = 0; j < 4; j++) {
        int idx = i0 + j;
        if (idx < GN) {
            int o = off[idx] + add;
            off[idx] = o;
            cur[idx] = o;
        }
    }
}

// ---------------- CSR fill: slot -> (src, norm) ------------------------------
__global__ void k_fill(const int* __restrict__ src, const int* __restrict__ dst,
                       const float* __restrict__ dinv,
                       int* cur, int* csrc, float* cnrm) {
    int e = blockIdx.x * blockDim.x + threadIdx.x;
    if (e >= GE) return;
    int s = __ldg(&src[e]);
    int d = __ldg(&dst[e]);
    int p = atomicAdd(&cur[d], 1);
    csrc[p] = s;
    cnrm[p] = __ldg(&dinv[s]) * __ldg(&dinv[d]);
}

// ---------------- GEMM 1: hw1 = [x | pos] @ W1  (K=80, Nout=64) -------------
#define KHP  81
#define G1_ROWS 64
__global__ __launch_bounds__(128) void k_gemm1(
    const float* __restrict__ x, const float* __restrict__ pos,
    const float* __restrict__ W1, const float* __restrict__ b1,
    const float* __restrict__ dinv,
    float* __restrict__ hw1, float* __restrict__ agg1)
{
    __shared__ float sW[KH * HID];
    __shared__ float sX[G1_ROWS * KHP];
    const int t = threadIdx.x;
    const int row0 = blockIdx.x * G1_ROWS;

    for (int i = t; i < KH * HID; i += 128) sW[i] = W1[i];
    for (int i = t; i < G1_ROWS * INC; i += 128) {
        int r = i >> 6, c = i & 63;
        int gr = row0 + r;
        sX[r * KHP + c] = (gr < GN) ? x[gr * INC + c] : 0.0f;
    }
    for (int i = t; i < G1_ROWS * POSC; i += 128) {
        int r = i >> 4, c = i & 15;
        int gr = row0 + r;
        sX[r * KHP + INC + c] = (gr < GN) ? pos[gr * POSC + c] : 0.0f;
    }
    __syncthreads();

    const int tx = t & 7;
    const int ty = t >> 3;
    float acc[4][8];
#pragma unroll
    for (int r = 0; r < 4; r++)
#pragma unroll
        for (int c = 0; c < 8; c++) acc[r][c] = 0.0f;

#pragma unroll 4
    for (int k = 0; k < KH; k++) {
        float4 w0 = *(const float4*)&sW[k * HID + tx * 8];
        float4 w1 = *(const float4*)&sW[k * HID + tx * 8 + 4];
#pragma unroll
        for (int r = 0; r < 4; r++) {
            float xv = sX[(ty * 4 + r) * KHP + k];
            acc[r][0] += xv * w0.x; acc[r][1] += xv * w0.y;
            acc[r][2] += xv * w0.z; acc[r][3] += xv * w0.w;
            acc[r][4] += xv * w1.x; acc[r][5] += xv * w1.y;
            acc[r][6] += xv * w1.z; acc[r][7] += xv * w1.w;
        }
    }

    float bb[8];
#pragma unroll
    for (int c = 0; c < 8; c++) bb[c] = __ldg(&b1[tx * 8 + c]);

#pragma unroll
    for (int r = 0; r < 4; r++) {
        int gr = row0 + ty * 4 + r;
        if (gr < GN) {
            float dv = __ldg(&dinv[gr]);
            float s = dv * dv;
            *(float4*)&hw1[gr * HID + tx * 8] =
                make_float4(acc[r][0], acc[r][1], acc[r][2], acc[r][3]);
            *(float4*)&hw1[gr * HID + tx * 8 + 4] =
                make_float4(acc[r][4], acc[r][5], acc[r][6], acc[r][7]);
            *(float4*)&agg1[gr * HID + tx * 8] =
                make_float4(bb[0] + acc[r][0] * s, bb[1] + acc[r][1] * s,
                            bb[2] + acc[r][2] * s, bb[3] + acc[r][3] * s);
            *(float4*)&agg1[gr * HID + tx * 8 + 4] =
                make_float4(bb[4] + acc[r][4] * s, bb[5] + acc[r][5] * s,
                            bb[6] + acc[r][6] * s, bb[7] + acc[r][7] * s);
        }
    }
}

// ---------------- GEMM 2: hw2 = relu(agg1) @ W2  (K=64, Nout=32) ------------
#define HIDP 65
#define G2_ROWS 128
__global__ __launch_bounds__(128) void k_gemm2(
    const float* __restrict__ h, const float* __restrict__ W2,
    const float* __restrict__ b2, const float* __restrict__ dinv,
    float* __restrict__ hw2, float* __restrict__ z)
{
    __shared__ float sW[HID * OUTC];
    __shared__ float sH[G2_ROWS * HIDP];
    const int t = threadIdx.x;
    const int row0 = blockIdx.x * G2_ROWS;

    for (int i = t; i < HID * OUTC; i += 128) sW[i] = W2[i];
    for (int i = t; i < G2_ROWS * HID; i += 128) {
        int r = i >> 6, c = i & 63;
        int gr = row0 + r;
        float v = (gr < GN) ? h[gr * HID + c] : 0.0f;
        sH[r * HIDP + c] = v > 0.0f ? v : 0.0f;       // fused ReLU
    }
    __syncthreads();

    const int tx = t & 3;
    const int ty = t >> 2;
    float acc[4][8];
#pragma unroll
    for (int r = 0; r < 4; r++)
#pragma unroll
        for (int c = 0; c < 8; c++) acc[r][c] = 0.0f;

#pragma unroll 4
    for (int k = 0; k < HID; k++) {
        float4 w0 = *(const float4*)&sW[k * OUTC + tx * 8];
        float4 w1 = *(const float4*)&sW[k * OUTC + tx * 8 + 4];
#pragma unroll
        for (int r = 0; r < 4; r++) {
            float hv = sH[(ty * 4 + r) * HIDP + k];
            acc[r][0] += hv * w0.x; acc[r][1] += hv * w0.y;
            acc[r][2] += hv * w0.z; acc[r][3] += hv * w0.w;
            acc[r][4] += hv * w1.x; acc[r][5] += hv * w1.y;
            acc[r][6] += hv * w1.z; acc[r][7] += hv * w1.w;
        }
    }

    float bb[8];
#pragma unroll
    for (int c = 0; c < 8; c++) bb[c] = __ldg(&b2[tx * 8 + c]);

#pragma unroll
    for (int r = 0; r < 4; r++) {
        int gr = row0 + ty * 4 + r;
        if (gr < GN) {
            float dv = __ldg(&dinv[gr]);
            float s = dv * dv;
            *(float4*)&hw2[gr * OUTC + tx * 8] =
                make_float4(acc[r][0], acc[r][1], acc[r][2], acc[r][3]);
            *(float4*)&hw2[gr * OUTC + tx * 8 + 4] =
                make_float4(acc[r][4], acc[r][5], acc[r][6], acc[r][7]);
            *(float4*)&z[gr * OUTC + tx * 8] =
                make_float4(bb[0] + acc[r][0] * s, bb[1] + acc[r][1] * s,
                            bb[2] + acc[r][2] * s, bb[3] + acc[r][3] * s);
            *(float4*)&z[gr * OUTC + tx * 8 + 4] =
                make_float4(bb[4] + acc[r][4] * s, bb[5] + acc[r][5] * s,
                            bb[6] + acc[r][6] * s, bb[7] + acc[r][7] * s);
        }
    }
}

// ---------------- CSR aggregation (atomic-free) ------------------------------
// One warp per dst node. out already holds the self-loop+bias init; we add the
// neighbor sum. Neighbor indices/norms preloaded 32-wide, shfl-broadcast.
__global__ __launch_bounds__(256) void k_agg_csr64(
    const float* __restrict__ hw, float* __restrict__ out,
    const int* __restrict__ off, const int* __restrict__ cnt,
    const int* __restrict__ csrc, const float* __restrict__ cnrm)
{
    int w = (blockIdx.x * blockDim.x + threadIdx.x) >> 5;
    int lane = threadIdx.x & 31;
    if (w >= GN) return;
    int n = __ldg(&cnt[w]);
    if (n == 0) return;
    int start = __ldg(&off[w]);
    float a0 = 0.0f, a1 = 0.0f;
    for (int base = 0; base < n; base += 32) {
        int m = n - base; if (m > 32) m = 32;
        int   sj = (lane < m) ? __ldg(&csrc[start + base + lane]) : 0;
        float fj = (lane < m) ? __ldg(&cnrm[start + base + lane]) : 0.0f;
        int j = 0;
        for (; j + 2 <= m; j += 2) {
            int   s0 = __shfl_sync(0xffffffffu, sj, j);
            float n0 = __shfl_sync(0xffffffffu, fj, j);
            int   s1 = __shfl_sync(0xffffffffu, sj, j + 1);
            float n1 = __shfl_sync(0xffffffffu, fj, j + 1);
            float v00 = __ldg(&hw[s0 * HID + lane]);
            float v01 = __ldg(&hw[s0 * HID + 32 + lane]);
            float v10 = __ldg(&hw[s1 * HID + lane]);
            float v11 = __ldg(&hw[s1 * HID + 32 + lane]);
            a0 += v00 * n0; a1 += v01 * n0;
            a0 += v10 * n1; a1 += v11 * n1;
        }
        if (j < m) {
            int   s0 = __shfl_sync(0xffffffffu, sj, j);
            float n0 = __shfl_sync(0xffffffffu, fj, j);
            a0 += __ldg(&hw[s0 * HID + lane]) * n0;
            a1 += __ldg(&hw[s0 * HID + 32 + lane]) * n0;
        }
    }
    out[w * HID + lane]      += a0;
    out[w * HID + 32 + lane] += a1;
}

__global__ __launch_bounds__(256) void k_agg_csr32(
    const float* __restrict__ hw, float* __restrict__ out,
    const int* __restrict__ off, const int* __restrict__ cnt,
    const int* __restrict__ csrc, const float* __restrict__ cnrm)
{
    int w = (blockIdx.x * blockDim.x + threadIdx.x) >> 5;
    int lane = threadIdx.x & 31;
    if (w >= GN) return;
    int n = __ldg(&cnt[w]);
    if (n == 0) return;
    int start = __ldg(&off[w]);
    float a0 = 0.0f;
    for (int base = 0; base < n; base += 32) {
        int m = n - base; if (m > 32) m = 32;
        int   sj = (lane < m) ? __ldg(&csrc[start + base + lane]) : 0;
        float fj = (lane < m) ? __ldg(&cnrm[start + base + lane]) : 0.0f;
        int j = 0;
        for (; j + 4 <= m; j += 4) {
            int   s0 = __shfl_sync(0xffffffffu, sj, j);
            float n0 = __shfl_sync(0xffffffffu, fj, j);
            int   s1 = __shfl_sync(0xffffffffu, sj, j + 1);
            float n1 = __shfl_sync(0xffffffffu, fj, j + 1);
            int   s2 = __shfl_sync(0xffffffffu, sj, j + 2);
            float n2 = __shfl_sync(0xffffffffu, fj, j + 2);
            int   s3 = __shfl_sync(0xffffffffu, sj, j + 3);
            float n3 = __shfl_sync(0xffffffffu, fj, j + 3);
            float v0 = __ldg(&hw[s0 * OUTC + lane]);
            float v1 = __ldg(&hw[s1 * OUTC + lane]);
            float v2 = __ldg(&hw[s2 * OUTC + lane]);
            float v3 = __ldg(&hw[s3 * OUTC + lane]);
            a0 += v0 * n0 + v1 * n1 + v2 * n2 + v3 * n3;
        }
        for (; j < m; j++) {
            int   s0 = __shfl_sync(0xffffffffu, sj, j);
            float n0 = __shfl_sync(0xffffffffu, fj, j);
            a0 += __ldg(&hw[s0 * OUTC + lane]) * n0;
        }
    }
    out[w * OUTC + lane] += a0;
}

// ---------------- link head: wa = z.Wl[0:32], wb = z.Wl[32:64] --------------
__global__ void k_wab(const float* __restrict__ z, const float* __restrict__ Wl,
                      float* __restrict__ wa, float* __restrict__ wb)
{
    __shared__ float sWl[2 * OUTC];
    int t = threadIdx.x;
    if (t < 2 * OUTC) sWl[t] = Wl[t];
    __syncthreads();
    int i = blockIdx.x * blockDim.x + t;
    if (i >= GN) return;
    const float4* zr = (const float4*)&z[i * OUTC];
    float a = 0.0f, b = 0.0f;
#pragma unroll
    for (int q = 0; q < OUTC / 4; q++) {
        float4 v = zr[q];
        a += v.x * sWl[q*4+0] + v.y * sWl[q*4+1] + v.z * sWl[q*4+2] + v.w * sWl[q*4+3];
        b += v.x * sWl[OUTC+q*4+0] + v.y * sWl[OUTC+q*4+1]
           + v.z * sWl[OUTC+q*4+2] + v.w * sWl[OUTC+q*4+3];
    }
    wa[i] = a; wb[i] = b;
}

__global__ void k_pred(const float* __restrict__ wa, const float* __restrict__ wb,
                       const int* __restrict__ sl, const int* __restrict__ dl,
                       const float* __restrict__ bl, float* __restrict__ pred)
{
    int i = blockIdx.x * blockDim.x + threadIdx.x;
    if (i >= GEL) return;
    pred[i] = wa[__ldg(&sl[i])] + wb[__ldg(&dl[i])] + bl[0];
}

// ---------------- launch -----------------------------------------------------
extern "C" void kernel_launch(void* const* d_in, const int* in_sizes, int n_in,
                              void* d_out, int out_size)
{
    const float* x    = (const float*)d_in[0];
    const float* pos  = (const float*)d_in[1];
    const float* W1   = (const float*)d_in[2];
    const float* b1   = (const float*)d_in[3];
    const float* W2   = (const float*)d_in[4];
    const float* b2   = (const float*)d_in[5];
    const float* Wl   = (const float*)d_in[6];
    const float* bl   = (const float*)d_in[7];
    const int*   ei   = (const int*)d_in[8];   // [2, E]: src row then dst row
    const int*   eli  = (const int*)d_in[9];   // [2, EL]

    const int* src = ei;
    const int* dst = ei + GE;
    const int* sl  = eli;
    const int* dl  = eli + GEL;

    float* z    = (float*)d_out;               // [N, OUTC]
    float* pred = z + (size_t)GN * OUTC;       // [EL]

    float *dinv, *hw1, *agg1, *hw2, *wa, *wb, *cnrm;
    int *cnt, *off, *cur, *bsum, *bscan, *csrc;
    cudaGetSymbolAddress((void**)&dinv,  g_dinv);
    cudaGetSymbolAddress((void**)&hw1,   g_hw1);
    cudaGetSymbolAddress((void**)&agg1,  g_agg1);
    cudaGetSymbolAddress((void**)&hw2,   g_hw2);
    cudaGetSymbolAddress((void**)&wa,    g_wa);
    cudaGetSymbolAddress((void**)&wb,    g_wb);
    cudaGetSymbolAddress((void**)&cnt,   g_cnt);
    cudaGetSymbolAddress((void**)&off,   g_off);
    cudaGetSymbolAddress((void**)&cur,   g_cur);
    cudaGetSymbolAddress((void**)&bsum,  g_bsum);
    cudaGetSymbolAddress((void**)&bscan, g_bscan);
    cudaGetSymbolAddress((void**)&csrc,  g_csrc);
    cudaGetSymbolAddress((void**)&cnrm,  g_cnrm);

    const int B = 256;

    // ---- CSR build: histogram -> scan -> dinv -> scatter fill
    k_zero_cnt<<<(GN + B - 1) / B, B>>>(cnt);
    k_hist<<<(GE + B - 1) / B, B>>>(dst, cnt);
    k_scan_local<<<NB, 256>>>(cnt, off, bsum);
    k_scan_bsum<<<1, 128>>>(bsum, bscan);
    k_scan_add<<<NB, 256>>>(off, cur, bscan);
    k_dinv<<<(GN + B - 1) / B, B>>>(cnt, dinv);
    k_fill<<<(GE + B - 1) / B, B>>>(src, dst, dinv, cur, csrc, cnrm);

    // ---- layer 1 (self-loop + bias init fused into gemm epilogue)
    k_gemm1<<<(GN + G1_ROWS - 1) / G1_ROWS, 128>>>(x, pos, W1, b1, dinv, hw1, agg1);
    k_agg_csr64<<<(GN * 32 + B - 1) / B, B>>>(hw1, agg1, off, cnt, csrc, cnrm);

    // ---- layer 2 (ReLU fused into gemm2 smem load; init fused into epilogue)
    k_gemm2<<<(GN + G2_ROWS - 1) / G2_ROWS, 128>>>(agg1, W2, b2, dinv, hw2, z);
    k_agg_csr32<<<(GN * 32 + B - 1) / B, B>>>(hw2, z, off, cnt, csrc, cnrm);

    // ---- link-prediction head: pred = z[s].Wl_top + z[d].Wl_bot + bl
    k_wab<<<(GN + B - 1) / B, B>>>(z, Wl, wa, wb);
    k_pred<<<(GEL + B - 1) / B, B>>>(wa, wb, sl, dl, bl, pred);
}

// round 8
// speedup vs baseline: 1.6269x; 1.6269x over previous
#include <cuda_runtime.h>
#include <cstdint>

// Problem constants (fixed shapes for this problem instance)
#define GN   100000      // nodes
#define GE   1600000     // edges
#define GEL  200000      // label edges
#define INC  64
#define POSC 16
#define KH   80          // INC + POSC
#define HID  64
#define OUTC 32
#define NB   98          // scan blocks: ceil(GN / 1024)

// ---------------- scratch (device globals; no allocation allowed) -----------
__device__ float g_dinv[GN];
__device__ float g_hw1 [GN * HID];
__device__ float g_agg1[GN * HID];
__device__ float g_hw2 [GN * OUTC];
__device__ float g_wa  [GN];
__device__ float g_wb  [GN];
__device__ int   g_cnt [GN];        // incoming-degree (no self-loop)
__device__ int   g_cur [GN];        // scatter cursor
__device__ int   g_bsum[128];
__device__ int   g_bscan[128];
__device__ int   g_csrc[GE];        // dst-sorted edge list: src
__device__ int   g_cdst[GE];        // dst-sorted edge list: dst
__device__ float g_cnrm[GE];        // dst-sorted edge list: dinv[s]*dinv[d]

// ---------------- degree histogram + normalization --------------------------
__global__ void k_zero_cnt(int* cnt) {
    int i = blockIdx.x * blockDim.x + threadIdx.x;
    if (i < GN) cnt[i] = 0;
}

__global__ void k_hist(const int* __restrict__ dst, int* cnt) {
    int i = blockIdx.x * blockDim.x + threadIdx.x;
    if (i < GE) atomicAdd(&cnt[dst[i]], 1);
}

__global__ void k_dinv(const int* __restrict__ cnt, float* dinv) {
    int i = blockIdx.x * blockDim.x + threadIdx.x;
    if (i < GN) dinv[i] = rsqrtf((float)(cnt[i] + 1));   // +1 self-loop
}

// ---------------- exclusive scan of cnt -> cur (3 kernels) ------------------
__global__ void k_scan_local(const int* __restrict__ cnt, int* off, int* bsum) {
    __shared__ int s[256];
    const int b = blockIdx.x, t = threadIdx.x;
    const int i0 = b * 1024 + t * 4;
    int v[4]; int sum = 0;
#pragma unroll
    for (int j = 0; j < 4; j++) {
        int idx = i0 + j;
        int c = (idx < GN) ? cnt[idx] : 0;
        v[j] = sum; sum += c;
    }
    s[t] = sum;
    __syncthreads();
    for (int d = 1; d < 256; d <<= 1) {
        int x = (t >= d) ? s[t - d] : 0;
        __syncthreads();
        s[t] += x;
        __syncthreads();
    }
    int base = (t > 0) ? s[t - 1] : 0;
#pragma unroll
    for (int j = 0; j < 4; j++) {
        int idx = i0 + j;
        if (idx < GN) off[idx] = base + v[j];
    }
    if (t == 255) bsum[b] = s[255];
}

__global__ void k_scan_bsum(const int* __restrict__ bsum, int* bscan) {
    __shared__ int s[128];
    int t = threadIdx.x;
    s[t] = (t < NB) ? bsum[t] : 0;
    __syncthreads();
    for (int d = 1; d < 128; d <<= 1) {
        int x = (t >= d) ? s[t - d] : 0;
        __syncthreads();
        s[t] += x;
        __syncthreads();
    }
    if (t < NB) bscan[t] = (t > 0) ? s[t - 1] : 0;
}

__global__ void k_scan_add(int* cur, const int* __restrict__ bscan) {
    const int b = blockIdx.x, t = threadIdx.x;
    const int add = bscan[b];
    const int i0 = b * 1024 + t * 4;
#pragma unroll
    for (int j = 0; j < 4; j++) {
        int idx = i0 + j;
        if (idx < GN) cur[idx] += add;
    }
}

// ---------------- fill dst-sorted edge list ----------------------------------
__global__ void k_fill(const int* __restrict__ src, const int* __restrict__ dst,
                       const float* __restrict__ dinv,
                       int* cur, int* csrc, int* cdst, float* cnrm) {
    int e = blockIdx.x * blockDim.x + threadIdx.x;
    if (e >= GE) return;
    int s = __ldg(&src[e]);
    int d = __ldg(&dst[e]);
    int p = atomicAdd(&cur[d], 1);
    csrc[p] = s;
    cdst[p] = d;
    cnrm[p] = __ldg(&dinv[s]) * __ldg(&dinv[d]);
}

// ---------------- GEMM 1: hw1 = [x | pos] @ W1  (K=80, Nout=64) -------------
#define KHP  81
#define G1_ROWS 64
__global__ __launch_bounds__(128) void k_gemm1(
    const float* __restrict__ x, const float* __restrict__ pos,
    const float* __restrict__ W1, const float* __restrict__ b1,
    const float* __restrict__ dinv,
    float* __restrict__ hw1, float* __restrict__ agg1)
{
    __shared__ float sW[KH * HID];
    __shared__ float sX[G1_ROWS * KHP];
    const int t = threadIdx.x;
    const int row0 = blockIdx.x * G1_ROWS;

    for (int i = t; i < KH * HID; i += 128) sW[i] = W1[i];
    for (int i = t; i < G1_ROWS * INC; i += 128) {
        int r = i >> 6, c = i & 63;
        int gr = row0 + r;
        sX[r * KHP + c] = (gr < GN) ? x[gr * INC + c] : 0.0f;
    }
    for (int i = t; i < G1_ROWS * POSC; i += 128) {
        int r = i >> 4, c = i & 15;
        int gr = row0 + r;
        sX[r * KHP + INC + c] = (gr < GN) ? pos[gr * POSC + c] : 0.0f;
    }
    __syncthreads();

    const int tx = t & 7;
    const int ty = t >> 3;
    float acc[4][8];
#pragma unroll
    for (int r = 0; r < 4; r++)
#pragma unroll
        for (int c = 0; c < 8; c++) acc[r][c] = 0.0f;

#pragma unroll 4
    for (int k = 0; k < KH; k++) {
        float4 w0 = *(const float4*)&sW[k * HID + tx * 8];
        float4 w1 = *(const float4*)&sW[k * HID + tx * 8 + 4];
#pragma unroll
        for (int r = 0; r < 4; r++) {
            float xv = sX[(ty * 4 + r) * KHP + k];
            acc[r][0] += xv * w0.x; acc[r][1] += xv * w0.y;
            acc[r][2] += xv * w0.z; acc[r][3] += xv * w0.w;
            acc[r][4] += xv * w1.x; acc[r][5] += xv * w1.y;
            acc[r][6] += xv * w1.z; acc[r][7] += xv * w1.w;
        }
    }

    float bb[8];
#pragma unroll
    for (int c = 0; c < 8; c++) bb[c] = __ldg(&b1[tx * 8 + c]);

#pragma unroll
    for (int r = 0; r < 4; r++) {
        int gr = row0 + ty * 4 + r;
        if (gr < GN) {
            float dv = __ldg(&dinv[gr]);
            float s = dv * dv;
            *(float4*)&hw1[gr * HID + tx * 8] =
                make_float4(acc[r][0], acc[r][1], acc[r][2], acc[r][3]);
            *(float4*)&hw1[gr * HID + tx * 8 + 4] =
                make_float4(acc[r][4], acc[r][5], acc[r][6], acc[r][7]);
            *(float4*)&agg1[gr * HID + tx * 8] =
                make_float4(bb[0] + acc[r][0] * s, bb[1] + acc[r][1] * s,
                            bb[2] + acc[r][2] * s, bb[3] + acc[r][3] * s);
            *(float4*)&agg1[gr * HID + tx * 8 + 4] =
                make_float4(bb[4] + acc[r][4] * s, bb[5] + acc[r][5] * s,
                            bb[6] + acc[r][6] * s, bb[7] + acc[r][7] * s);
        }
    }
}

// ---------------- GEMM 2: hw2 = relu(agg1) @ W2  (K=64, Nout=32) ------------
#define HIDP 65
#define G2_ROWS 128
__global__ __launch_bounds__(128) void k_gemm2(
    const float* __restrict__ h, const float* __restrict__ W2,
    const float* __restrict__ b2, const float* __restrict__ dinv,
    float* __restrict__ hw2, float* __restrict__ z)
{
    __shared__ float sW[HID * OUTC];
    __shared__ float sH[G2_ROWS * HIDP];
    const int t = threadIdx.x;
    const int row0 = blockIdx.x * G2_ROWS;

    for (int i = t; i < HID * OUTC; i += 128) sW[i] = W2[i];
    for (int i = t; i < G2_ROWS * HID; i += 128) {
        int r = i >> 6, c = i & 63;
        int gr = row0 + r;
        float v = (gr < GN) ? h[gr * HID + c] : 0.0f;
        sH[r * HIDP + c] = v > 0.0f ? v : 0.0f;       // fused ReLU
    }
    __syncthreads();

    const int tx = t & 3;
    const int ty = t >> 2;
    float acc[4][8];
#pragma unroll
    for (int r = 0; r < 4; r++)
#pragma unroll
        for (int c = 0; c < 8; c++) acc[r][c] = 0.0f;

#pragma unroll 4
    for (int k = 0; k < HID; k++) {
        float4 w0 = *(const float4*)&sW[k * OUTC + tx * 8];
        float4 w1 = *(const float4*)&sW[k * OUTC + tx * 8 + 4];
#pragma unroll
        for (int r = 0; r < 4; r++) {
            float hv = sH[(ty * 4 + r) * HIDP + k];
            acc[r][0] += hv * w0.x; acc[r][1] += hv * w0.y;
            acc[r][2] += hv * w0.z; acc[r][3] += hv * w0.w;
            acc[r][4] += hv * w1.x; acc[r][5] += hv * w1.y;
            acc[r][6] += hv * w1.z; acc[r][7] += hv * w1.w;
        }
    }

    float bb[8];
#pragma unroll
    for (int c = 0; c < 8; c++) bb[c] = __ldg(&b2[tx * 8 + c]);

#pragma unroll
    for (int r = 0; r < 4; r++) {
        int gr = row0 + ty * 4 + r;
        if (gr < GN) {
            float dv = __ldg(&dinv[gr]);
            float s = dv * dv;
            *(float4*)&hw2[gr * OUTC + tx * 8] =
                make_float4(acc[r][0], acc[r][1], acc[r][2], acc[r][3]);
            *(float4*)&hw2[gr * OUTC + tx * 8 + 4] =
                make_float4(acc[r][4], acc[r][5], acc[r][6], acc[r][7]);
            *(float4*)&z[gr * OUTC + tx * 8] =
                make_float4(bb[0] + acc[r][0] * s, bb[1] + acc[r][1] * s,
                            bb[2] + acc[r][2] * s, bb[3] + acc[r][3] * s);
            *(float4*)&z[gr * OUTC + tx * 8 + 4] =
                make_float4(bb[4] + acc[r][4] * s, bb[5] + acc[r][5] * s,
                            bb[6] + acc[r][6] * s, bb[7] + acc[r][7] * s);
        }
    }
}

// ---------------- segmented edge aggregation over dst-sorted list ------------
// Block stages SB slots of (src, dst, nrm) in smem. Thread: one quad q of a
// window of W=16 consecutive slots; accumulates in registers while dst
// unchanged, red.global.add.v4 on segment change. Sorted order means ~2-3
// reds per window instead of 16. Gathers stay fully coalesced across quads.
template <int LOGQ, int SB>   // LOGQ=4 (64 feats) SB=256 ; LOGQ=3 (32) SB=512
__global__ __launch_bounds__(256) void k_agg_seg(
    const float4* __restrict__ vals, float4* __restrict__ out,
    const int* __restrict__ csrc, const int* __restrict__ cdst,
    const float* __restrict__ cnrm)
{
    __shared__ int   ssrc[SB];
    __shared__ int   sdst[SB];
    __shared__ float snrm[SB];
    const int t = threadIdx.x;
    const int s0 = blockIdx.x * SB;
    for (int i = t; i < SB; i += 256) {
        ssrc[i] = csrc[s0 + i];
        sdst[i] = cdst[s0 + i];
        snrm[i] = cnrm[s0 + i];
    }
    __syncthreads();

    const int q    = t & ((1 << LOGQ) - 1);
    const int base = (t >> LOGQ) * 16;          // window of 16 slots

    int cur = sdst[base];
    float ax = 0.0f, ay = 0.0f, az = 0.0f, aw = 0.0f;
#pragma unroll
    for (int j = 0; j < 16; j++) {
        int sd = sdst[base + j];
        if (sd != cur) {
            float4* p = &out[(cur << LOGQ) + q];
            asm volatile("red.global.add.v4.f32 [%0], {%1,%2,%3,%4};"
                         :: "l"(p), "f"(ax), "f"(ay), "f"(az), "f"(aw)
                         : "memory");
            ax = ay = az = aw = 0.0f;
            cur = sd;
        }
        float nm = snrm[base + j];
        float4 v = __ldg(&vals[(ssrc[base + j] << LOGQ) + q]);
        ax += v.x * nm; ay += v.y * nm; az += v.z * nm; aw += v.w * nm;
    }
    float4* p = &out[(cur << LOGQ) + q];
    asm volatile("red.global.add.v4.f32 [%0], {%1,%2,%3,%4};"
                 :: "l"(p), "f"(ax), "f"(ay), "f"(az), "f"(aw)
                 : "memory");
}

// ---------------- link head: wa = z.Wl[0:32], wb = z.Wl[32:64] --------------
__global__ void k_wab(const float* __restrict__ z, const float* __restrict__ Wl,
                      float* __restrict__ wa, float* __restrict__ wb)
{
    __shared__ float sWl[2 * OUTC];
    int t = threadIdx.x;
    if (t < 2 * OUTC) sWl[t] = Wl[t];
    __syncthreads();
    int i = blockIdx.x * blockDim.x + t;
    if (i >= GN) return;
    const float4* zr = (const float4*)&z[i * OUTC];
    float a = 0.0f, b = 0.0f;
#pragma unroll
    for (int q = 0; q < OUTC / 4; q++) {
        float4 v = zr[q];
        a += v.x * sWl[q*4+0] + v.y * sWl[q*4+1] + v.z * sWl[q*4+2] + v.w * sWl[q*4+3];
        b += v.x * sWl[OUTC+q*4+0] + v.y * sWl[OUTC+q*4+1]
           + v.z * sWl[OUTC+q*4+2] + v.w * sWl[OUTC+q*4+3];
    }
    wa[i] = a; wb[i] = b;
}

__global__ void k_pred(const float* __restrict__ wa, const float* __restrict__ wb,
                       const int* __restrict__ sl, const int* __restrict__ dl,
                       const float* __restrict__ bl, float* __restrict__ pred)
{
    int i = blockIdx.x * blockDim.x + threadIdx.x;
    if (i >= GEL) return;
    pred[i] = wa[__ldg(&sl[i])] + wb[__ldg(&dl[i])] + bl[0];
}

// ---------------- launch -----------------------------------------------------
extern "C" void kernel_launch(void* const* d_in, const int* in_sizes, int n_in,
                              void* d_out, int out_size)
{
    const float* x    = (const float*)d_in[0];
    const float* pos  = (const float*)d_in[1];
    const float* W1   = (const float*)d_in[2];
    const float* b1   = (const float*)d_in[3];
    const float* W2   = (const float*)d_in[4];
    const float* b2   = (const float*)d_in[5];
    const float* Wl   = (const float*)d_in[6];
    const float* bl   = (const float*)d_in[7];
    const int*   ei   = (const int*)d_in[8];   // [2, E]: src row then dst row
    const int*   eli  = (const int*)d_in[9];   // [2, EL]

    const int* src = ei;
    const int* dst = ei + GE;
    const int* sl  = eli;
    const int* dl  = eli + GEL;

    float* z    = (float*)d_out;               // [N, OUTC]
    float* pred = z + (size_t)GN * OUTC;       // [EL]

    float *dinv, *hw1, *agg1, *hw2, *wa, *wb, *cnrm;
    int *cnt, *cur, *bsum, *bscan, *csrc, *cdst;
    cudaGetSymbolAddress((void**)&dinv,  g_dinv);
    cudaGetSymbolAddress((void**)&hw1,   g_hw1);
    cudaGetSymbolAddress((void**)&agg1,  g_agg1);
    cudaGetSymbolAddress((void**)&hw2,   g_hw2);
    cudaGetSymbolAddress((void**)&wa,    g_wa);
    cudaGetSymbolAddress((void**)&wb,    g_wb);
    cudaGetSymbolAddress((void**)&cnt,   g_cnt);
    cudaGetSymbolAddress((void**)&cur,   g_cur);
    cudaGetSymbolAddress((void**)&bsum,  g_bsum);
    cudaGetSymbolAddress((void**)&bscan, g_bscan);
    cudaGetSymbolAddress((void**)&csrc,  g_csrc);
    cudaGetSymbolAddress((void**)&cdst,  g_cdst);
    cudaGetSymbolAddress((void**)&cnrm,  g_cnrm);

    const int B = 256;

    // ---- build dst-sorted edge list: histogram -> scan -> dinv -> fill
    k_zero_cnt<<<(GN + B - 1) / B, B>>>(cnt);
    k_hist<<<(GE + B - 1) / B, B>>>(dst, cnt);
    k_scan_local<<<NB, 256>>>(cnt, cur, bsum);
    k_scan_bsum<<<1, 128>>>(bsum, bscan);
    k_scan_add<<<NB, 256>>>(cur, bscan);
    k_dinv<<<(GN + B - 1) / B, B>>>(cnt, dinv);
    k_fill<<<(GE + B - 1) / B, B>>>(src, dst, dinv, cur, csrc, cdst, cnrm);

    // ---- layer 1 (self-loop + bias init fused into gemm epilogue)
    k_gemm1<<<(GN + G1_ROWS - 1) / G1_ROWS, 128>>>(x, pos, W1, b1, dinv, hw1, agg1);
    k_agg_seg<4, 256><<<GE / 256, 256>>>((const float4*)hw1, (float4*)agg1,
                                         csrc, cdst, cnrm);

    // ---- layer 2 (ReLU fused into gemm2 smem load; init fused into epilogue)
    k_gemm2<<<(GN + G2_ROWS - 1) / G2_ROWS, 128>>>(agg1, W2, b2, dinv, hw2, z);
    k_agg_seg<3, 512><<<GE / 512, 256>>>((const float4*)hw2, (float4*)z,
                                         csrc, cdst, cnrm);

    // ---- link-prediction head: pred = z[s].Wl_top + z[d].Wl_bot + bl
    k_wab<<<(GN + B - 1) / B, B>>>(z, Wl, wa, wb);
    k_pred<<<(GEL + B - 1) / B, B>>>(wa, wb, sl, dl, bl, pred);
}

// round 9
// speedup vs baseline: 1.7014x; 1.0458x over previous
#include <cuda_runtime.h>
#include <cstdint>

// Problem constants (fixed shapes for this problem instance)
#define GN   100000      // nodes
#define GE   1600000     // edges
#define GEL  200000      // label edges
#define INC  64
#define POSC 16
#define KH   80          // INC + POSC
#define HID  64
#define OUTC 32
#define NB   98          // scan blocks: ceil(GN / 1024)

// ---------------- scratch (device globals; no allocation allowed) -----------
__device__ float g_dinv[GN];
__device__ float g_hw1 [GN * HID];
__device__ float g_agg1[GN * HID];
__device__ float g_hw2 [GN * OUTC];
__device__ float g_wa  [GN];
__device__ float g_wb  [GN];
__device__ int   g_cnt [GN];        // incoming-degree (no self-loop)
__device__ int   g_cur [GN];        // scatter cursor
__device__ int   g_bsum[128];
__device__ int   g_bscan[128];
__device__ int   g_csrc[GE];        // dst-sorted edge list: src
__device__ int   g_cdst[GE];        // dst-sorted edge list: dst
__device__ float g_cnrm[GE];        // dst-sorted edge list: dinv[s]*dinv[d]

// ---------------- degree histogram + normalization --------------------------
__global__ void k_zero_cnt(int* cnt) {
    int i = blockIdx.x * blockDim.x + threadIdx.x;
    if (i < GN) cnt[i] = 0;
}

__global__ void k_hist(const int* __restrict__ dst, int* cnt) {
    int i = blockIdx.x * blockDim.x + threadIdx.x;
    if (i < GE) atomicAdd(&cnt[dst[i]], 1);
}

__global__ void k_dinv(const int* __restrict__ cnt, float* dinv) {
    int i = blockIdx.x * blockDim.x + threadIdx.x;
    if (i < GN) dinv[i] = rsqrtf((float)(cnt[i] + 1));   // +1 self-loop
}

// ---------------- exclusive scan of cnt -> cur (3 kernels) ------------------
__global__ void k_scan_local(const int* __restrict__ cnt, int* off, int* bsum) {
    __shared__ int s[256];
    const int b = blockIdx.x, t = threadIdx.x;
    const int i0 = b * 1024 + t * 4;
    int v[4]; int sum = 0;
#pragma unroll
    for (int j = 0; j < 4; j++) {
        int idx = i0 + j;
        int c = (idx < GN) ? cnt[idx] : 0;
        v[j] = sum; sum += c;
    }
    s[t] = sum;
    __syncthreads();
    for (int d = 1; d < 256; d <<= 1) {
        int x = (t >= d) ? s[t - d] : 0;
        __syncthreads();
        s[t] += x;
        __syncthreads();
    }
    int base = (t > 0) ? s[t - 1] : 0;
#pragma unroll
    for (int j = 0; j < 4; j++) {
        int idx = i0 + j;
        if (idx < GN) off[idx] = base + v[j];
    }
    if (t == 255) bsum[b] = s[255];
}

__global__ void k_scan_bsum(const int* __restrict__ bsum, int* bscan) {
    __shared__ int s[128];
    int t = threadIdx.x;
    s[t] = (t < NB) ? bsum[t] : 0;
    __syncthreads();
    for (int d = 1; d < 128; d <<= 1) {
        int x = (t >= d) ? s[t - d] : 0;
        __syncthreads();
        s[t] += x;
        __syncthreads();
    }
    if (t < NB) bscan[t] = (t > 0) ? s[t - 1] : 0;
}

__global__ void k_scan_add(int* cur, const int* __restrict__ bscan) {
    const int b = blockIdx.x, t = threadIdx.x;
    const int add = bscan[b];
    const int i0 = b * 1024 + t * 4;
#pragma unroll
    for (int j = 0; j < 4; j++) {
        int idx = i0 + j;
        if (idx < GN) cur[idx] += add;
    }
}

// ---------------- fill dst-sorted edge list ----------------------------------
__global__ void k_fill(const int* __restrict__ src, const int* __restrict__ dst,
                       const float* __restrict__ dinv,
                       int* cur, int* csrc, int* cdst, float* cnrm) {
    int e = blockIdx.x * blockDim.x + threadIdx.x;
    if (e >= GE) return;
    int s = __ldg(&src[e]);
    int d = __ldg(&dst[e]);
    int p = atomicAdd(&cur[d], 1);
    csrc[p] = s;
    cdst[p] = d;
    cnrm[p] = __ldg(&dinv[s]) * __ldg(&dinv[d]);
}

// ---------------- GEMM 1: hw1 = [x | pos] @ W1  (K=80, Nout=64) -------------
// 64 rows per block, 256 threads. Thread: 4 rows x 4 cols. 40 warps/SM.
// No dinv dependency (init done separately) so it overlaps the CSR build.
#define KHP  81
#define G1_ROWS 64
__global__ __launch_bounds__(256) void k_gemm1(
    const float* __restrict__ x, const float* __restrict__ pos,
    const float* __restrict__ W1, float* __restrict__ hw1)
{
    __shared__ float sW[KH * HID];          // 20 KB
    __shared__ float sX[G1_ROWS * KHP];     // 20.7 KB (total 40.7 KB)
    const int t = threadIdx.x;
    const int row0 = blockIdx.x * G1_ROWS;

    for (int i = t; i < KH * HID; i += 256) sW[i] = W1[i];
    for (int i = t; i < G1_ROWS * INC; i += 256) {
        int r = i >> 6, c = i & 63;
        int gr = row0 + r;
        sX[r * KHP + c] = (gr < GN) ? x[gr * INC + c] : 0.0f;
    }
    for (int i = t; i < G1_ROWS * POSC; i += 256) {
        int r = i >> 4, c = i & 15;
        int gr = row0 + r;
        sX[r * KHP + INC + c] = (gr < GN) ? pos[gr * POSC + c] : 0.0f;
    }
    __syncthreads();

    const int tx = t & 15;   // 16 col groups x 4 = 64 cols
    const int ty = t >> 4;   // 16 row groups x 4 = 64 rows
    float acc[4][4];
#pragma unroll
    for (int r = 0; r < 4; r++)
#pragma unroll
        for (int c = 0; c < 4; c++) acc[r][c] = 0.0f;

#pragma unroll 4
    for (int k = 0; k < KH; k++) {
        float4 w = *(const float4*)&sW[k * HID + tx * 4];
#pragma unroll
        for (int r = 0; r < 4; r++) {
            float xv = sX[(ty * 4 + r) * KHP + k];
            acc[r][0] += xv * w.x; acc[r][1] += xv * w.y;
            acc[r][2] += xv * w.z; acc[r][3] += xv * w.w;
        }
    }
#pragma unroll
    for (int r = 0; r < 4; r++) {
        int gr = row0 + ty * 4 + r;
        if (gr < GN)
            *(float4*)&hw1[gr * HID + tx * 4] =
                make_float4(acc[r][0], acc[r][1], acc[r][2], acc[r][3]);
    }
}

// ---------------- layer-1 agg init: agg1 = b1 + hw1 * dinv^2 ----------------
__global__ void k_init1(const float4* __restrict__ hw, float4* __restrict__ out,
                        const float* __restrict__ b1, const float* __restrict__ dinv)
{
    int i = blockIdx.x * blockDim.x + threadIdx.x;
    if (i >= GN * 16) return;
    int node = i >> 4, q = i & 15;
    float dv = __ldg(&dinv[node]);
    float s = dv * dv;
    float4 v = __ldg(&hw[i]);
    float4 b = __ldg(&((const float4*)b1)[q]);
    out[i] = make_float4(b.x + v.x * s, b.y + v.y * s,
                         b.z + v.z * s, b.w + v.w * s);
}

// ---------------- GEMM 2: hw2 = relu(agg1) @ W2  (K=64, Nout=32) ------------
// 128 rows per block, 256 threads. Thread: 4 rows x 4 cols. 40 warps/SM.
// Epilogue writes z = b2 + hw2 * dinv^2 (dinv ready by now).
#define HIDP 65
#define G2_ROWS 128
__global__ __launch_bounds__(256) void k_gemm2(
    const float* __restrict__ h, const float* __restrict__ W2,
    const float* __restrict__ b2, const float* __restrict__ dinv,
    float* __restrict__ hw2, float* __restrict__ z)
{
    __shared__ float sW[HID * OUTC];        // 8 KB
    __shared__ float sH[G2_ROWS * HIDP];    // 33.3 KB (total 41.3 KB)
    const int t = threadIdx.x;
    const int row0 = blockIdx.x * G2_ROWS;

    for (int i = t; i < HID * OUTC; i += 256) sW[i] = W2[i];
    for (int i = t; i < G2_ROWS * HID; i += 256) {
        int r = i >> 6, c = i & 63;
        int gr = row0 + r;
        float v = (gr < GN) ? h[gr * HID + c] : 0.0f;
        sH[r * HIDP + c] = v > 0.0f ? v : 0.0f;       // fused ReLU
    }
    __syncthreads();

    const int tx = t & 7;    // 8 col groups x 4 = 32 cols
    const int ty = t >> 3;   // 32 row groups x 4 = 128 rows
    float acc[4][4];
#pragma unroll
    for (int r = 0; r < 4; r++)
#pragma unroll
        for (int c = 0; c < 4; c++) acc[r][c] = 0.0f;

#pragma unroll 4
    for (int k = 0; k < HID; k++) {
        float4 w = *(const float4*)&sW[k * OUTC + tx * 4];
#pragma unroll
        for (int r = 0; r < 4; r++) {
            float hv = sH[(ty * 4 + r) * HIDP + k];
            acc[r][0] += hv * w.x; acc[r][1] += hv * w.y;
            acc[r][2] += hv * w.z; acc[r][3] += hv * w.w;
        }
    }

    float4 b = __ldg(&((const float4*)b2)[tx]);
#pragma unroll
    for (int r = 0; r < 4; r++) {
        int gr = row0 + ty * 4 + r;
        if (gr < GN) {
            float dv = __ldg(&dinv[gr]);
            float s = dv * dv;
            *(float4*)&hw2[gr * OUTC + tx * 4] =
                make_float4(acc[r][0], acc[r][1], acc[r][2], acc[r][3]);
            *(float4*)&z[gr * OUTC + tx * 4] =
                make_float4(b.x + acc[r][0] * s, b.y + acc[r][1] * s,
                            b.z + acc[r][2] * s, b.w + acc[r][3] * s);
        }
    }
}

// ---------------- segmented edge aggregation over dst-sorted list ------------
template <int LOGQ, int SB>   // LOGQ=4 (64 feats) SB=256 ; LOGQ=3 (32) SB=512
__global__ __launch_bounds__(256) void k_agg_seg(
    const float4* __restrict__ vals, float4* __restrict__ out,
    const int* __restrict__ csrc, const int* __restrict__ cdst,
    const float* __restrict__ cnrm)
{
    __shared__ int   ssrc[SB];
    __shared__ int   sdst[SB];
    __shared__ float snrm[SB];
    const int t = threadIdx.x;
    const int s0 = blockIdx.x * SB;
    for (int i = t; i < SB; i += 256) {
        ssrc[i] = csrc[s0 + i];
        sdst[i] = cdst[s0 + i];
        snrm[i] = cnrm[s0 + i];
    }
    __syncthreads();

    const int q    = t & ((1 << LOGQ) - 1);
    const int base = (t >> LOGQ) * 16;          // window of 16 slots

    int cur = sdst[base];
    float ax = 0.0f, ay = 0.0f, az = 0.0f, aw = 0.0f;
#pragma unroll
    for (int j = 0; j < 16; j++) {
        int sd = sdst[base + j];
        if (sd != cur) {
            float4* p = &out[(cur << LOGQ) + q];
            asm volatile("red.global.add.v4.f32 [%0], {%1,%2,%3,%4};"
                         :: "l"(p), "f"(ax), "f"(ay), "f"(az), "f"(aw)
                         : "memory");
            ax = ay = az = aw = 0.0f;
            cur = sd;
        }
        float nm = snrm[base + j];
        float4 v = __ldg(&vals[(ssrc[base + j] << LOGQ) + q]);
        ax += v.x * nm; ay += v.y * nm; az += v.z * nm; aw += v.w * nm;
    }
    float4* p = &out[(cur << LOGQ) + q];
    asm volatile("red.global.add.v4.f32 [%0], {%1,%2,%3,%4};"
                 :: "l"(p), "f"(ax), "f"(ay), "f"(az), "f"(aw)
                 : "memory");
}

// ---------------- link head: wa = z.Wl[0:32], wb = z.Wl[32:64] --------------
__global__ void k_wab(const float* __restrict__ z, const float* __restrict__ Wl,
                      float* __restrict__ wa, float* __restrict__ wb)
{
    __shared__ float sWl[2 * OUTC];
    int t = threadIdx.x;
    if (t < 2 * OUTC) sWl[t] = Wl[t];
    __syncthreads();
    int i = blockIdx.x * blockDim.x + t;
    if (i >= GN) return;
    const float4* zr = (const float4*)&z[i * OUTC];
    float a = 0.0f, b = 0.0f;
#pragma unroll
    for (int q = 0; q < OUTC / 4; q++) {
        float4 v = zr[q];
        a += v.x * sWl[q*4+0] + v.y * sWl[q*4+1] + v.z * sWl[q*4+2] + v.w * sWl[q*4+3];
        b += v.x * sWl[OUTC+q*4+0] + v.y * sWl[OUTC+q*4+1]
           + v.z * sWl[OUTC+q*4+2] + v.w * sWl[OUTC+q*4+3];
    }
    wa[i] = a; wb[i] = b;
}

__global__ void k_pred(const float* __restrict__ wa, const float* __restrict__ wb,
                       const int* __restrict__ sl, const int* __restrict__ dl,
                       const float* __restrict__ bl, float* __restrict__ pred)
{
    int i = blockIdx.x * blockDim.x + threadIdx.x;
    if (i >= GEL) return;
    pred[i] = wa[__ldg(&sl[i])] + wb[__ldg(&dl[i])] + bl[0];
}

// ---------------- launch -----------------------------------------------------
extern "C" void kernel_launch(void* const* d_in, const int* in_sizes, int n_in,
                              void* d_out, int out_size)
{
    const float* x    = (const float*)d_in[0];
    const float* pos  = (const float*)d_in[1];
    const float* W1   = (const float*)d_in[2];
    const float* b1   = (const float*)d_in[3];
    const float* W2   = (const float*)d_in[4];
    const float* b2   = (const float*)d_in[5];
    const float* Wl   = (const float*)d_in[6];
    const float* bl   = (const float*)d_in[7];
    const int*   ei   = (const int*)d_in[8];   // [2, E]: src row then dst row
    const int*   eli  = (const int*)d_in[9];   // [2, EL]

    const int* src = ei;
    const int* dst = ei + GE;
    const int* sl  = eli;
    const int* dl  = eli + GEL;

    float* z    = (float*)d_out;               // [N, OUTC]
    float* pred = z + (size_t)GN * OUTC;       // [EL]

    float *dinv, *hw1, *agg1, *hw2, *wa, *wb, *cnrm;
    int *cnt, *cur, *bsum, *bscan, *csrc, *cdst;
    cudaGetSymbolAddress((void**)&dinv,  g_dinv);
    cudaGetSymbolAddress((void**)&hw1,   g_hw1);
    cudaGetSymbolAddress((void**)&agg1,  g_agg1);
    cudaGetSymbolAddress((void**)&hw2,   g_hw2);
    cudaGetSymbolAddress((void**)&wa,    g_wa);
    cudaGetSymbolAddress((void**)&wb,    g_wb);
    cudaGetSymbolAddress((void**)&cnt,   g_cnt);
    cudaGetSymbolAddress((void**)&cur,   g_cur);
    cudaGetSymbolAddress((void**)&bsum,  g_bsum);
    cudaGetSymbolAddress((void**)&bscan, g_bscan);
    cudaGetSymbolAddress((void**)&csrc,  g_csrc);
    cudaGetSymbolAddress((void**)&cdst,  g_cdst);
    cudaGetSymbolAddress((void**)&cnrm,  g_cnrm);

    const int B = 256;

    // Fork: CSR build on a side stream, gemm1 (independent) on the main stream.
    cudaStream_t side;
    cudaStreamCreateWithFlags(&side, cudaStreamNonBlocking);
    cudaEvent_t evF, evJ;
    cudaEventCreateWithFlags(&evF, cudaEventDisableTiming);
    cudaEventCreateWithFlags(&evJ, cudaEventDisableTiming);

    cudaEventRecord(evF, 0);
    cudaStreamWaitEvent(side, evF, 0);

    // ---- side stream: histogram -> scan -> dinv -> dst-sorted fill
    k_zero_cnt<<<(GN + B - 1) / B, B, 0, side>>>(cnt);
    k_hist<<<(GE + B - 1) / B, B, 0, side>>>(dst, cnt);
    k_scan_local<<<NB, 256, 0, side>>>(cnt, cur, bsum);
    k_scan_bsum<<<1, 128, 0, side>>>(bsum, bscan);
    k_scan_add<<<NB, 256, 0, side>>>(cur, bscan);
    k_dinv<<<(GN + B - 1) / B, B, 0, side>>>(cnt, dinv);
    k_fill<<<(GE + B - 1) / B, B, 0, side>>>(src, dst, dinv, cur, csrc, cdst, cnrm);
    cudaEventRecord(evJ, side);

    // ---- main stream: gemm1 runs concurrently with the build
    k_gemm1<<<(GN + G1_ROWS - 1) / G1_ROWS, 256>>>(x, pos, W1, hw1);

    // Join: everything below needs the build outputs.
    cudaStreamWaitEvent(0, evJ, 0);

    // ---- layer 1
    k_init1<<<(GN * 16 + B - 1) / B, B>>>((const float4*)hw1, (float4*)agg1, b1, dinv);
    k_agg_seg<4, 256><<<GE / 256, 256>>>((const float4*)hw1, (float4*)agg1,
                                         csrc, cdst, cnrm);

    // ---- layer 2 (ReLU fused into gemm2 smem load; z init fused in epilogue)
    k_gemm2<<<(GN + G2_ROWS - 1) / G2_ROWS, 256>>>(agg1, W2, b2, dinv, hw2, z);
    k_agg_seg<3, 512><<<GE / 512, 256>>>((const float4*)hw2, (float4*)z,
                                         csrc, cdst, cnrm);

    // ---- link-prediction head: pred = z[s].Wl_top + z[d].Wl_bot + bl
    k_wab<<<(GN + B - 1) / B, B>>>(z, Wl, wa, wb);
    k_pred<<<(GEL + B - 1) / B, B>>>(wa, wb, sl, dl, bl, pred);
}